// round 5
// baseline (speedup 1.0000x reference)
#include <cuda_runtime.h>
#include <math.h>
#include <stdint.h>

// Problem constants
#define Bn   8
#define Hh   32
#define Ww   32
#define Cc   192
#define DI   384
#define Ss   16
#define Rr   12
#define HID  768
#define Ll   1024          // H*W
#define ROWS (Bn * Ll)     // 8192

// ---------------- scratch (no allocation allowed) ----------------
__device__ float g_hx   [ROWS * Cc];
__device__ float g_xz   [ROWS * (2 * DI)];
__device__ float g_u    [ROWS * DI];
__device__ float g_xw64 [64 * DI];       // padded x_proj_w
__device__ float g_xdbl [ROWS * 64];     // padded x_dbl (cols 0..43 valid)
__device__ float g_delta[ROWS * DI];
__device__ float g_y    [ROWS * DI];
__device__ float g_xmid [ROWS * Cc];
__device__ float g_h2   [ROWS * Cc];
__device__ float g_m    [ROWS * HID];

// ---------------- device math helpers ----------------
__device__ __forceinline__ float silu_f(float x) {
    return x / (1.0f + __expf(-x));
}
__device__ __forceinline__ float softplus_f(float x) {
    return (x > 20.0f) ? x : log1pf(expf(x));
}
__device__ __forceinline__ float gelu_f(float x) {
    float x3 = x * x * x;
    return 0.5f * x * (1.0f + tanhf(0.7978845608028654f * (x + 0.044715f * x3)));
}
__device__ __forceinline__ uint32_t tf32_of(float x) {
    uint32_t r;
    asm("cvt.rna.tf32.f32 %0, %1;" : "=r"(r) : "f"(x));
    return r;
}
__device__ __forceinline__ void mma_tf32(float& c0, float& c1, float& c2, float& c3,
                                         uint32_t a0, uint32_t a1, uint32_t a2, uint32_t a3,
                                         uint32_t b0, uint32_t b1) {
    asm volatile(
        "mma.sync.aligned.m16n8k8.row.col.f32.tf32.tf32.f32 "
        "{%0,%1,%2,%3}, {%4,%5,%6,%7}, {%8,%9}, {%0,%1,%2,%3};\n"
        : "+f"(c0), "+f"(c1), "+f"(c2), "+f"(c3)
        : "r"(a0), "r"(a1), "r"(a2), "r"(a3), "r"(b0), "r"(b1));
}

// ---------------- LayerNorm (one block per row, blockDim == C) ----------------
template <int C>
__global__ void ln_kernel(const float* __restrict__ x,
                          const float* __restrict__ g,
                          const float* __restrict__ b,
                          float* __restrict__ out) {
    int row = blockIdx.x;
    int t   = threadIdx.x;
    float v = x[row * C + t];
    float s = v, s2 = v * v;
    __shared__ float sh[C / 32], sh2[C / 32];
#pragma unroll
    for (int o = 16; o; o >>= 1) {
        s  += __shfl_xor_sync(0xffffffffu, s,  o);
        s2 += __shfl_xor_sync(0xffffffffu, s2, o);
    }
    if ((t & 31) == 0) { sh[t >> 5] = s; sh2[t >> 5] = s2; }
    __syncthreads();
    float mean = 0.f, m2 = 0.f;
#pragma unroll
    for (int i = 0; i < C / 32; i++) { mean += sh[i]; m2 += sh2[i]; }
    mean *= (1.0f / C);
    float var = m2 * (1.0f / C) - mean * mean;
    float inv = rsqrtf(var + 1e-5f);
    out[row * C + t] = (v - mean) * inv * g[t] + b[t];
}

// ---------------- out_norm LN + silu(z) gating (C = DI = 384) ----------------
__global__ void gate_ln_kernel(const float* __restrict__ y,
                               const float* __restrict__ xz,
                               const float* __restrict__ g,
                               const float* __restrict__ b,
                               float* __restrict__ out) {
    int row = blockIdx.x;
    int t   = threadIdx.x;           // 384
    float v = y[row * DI + t];
    float s = v, s2 = v * v;
    __shared__ float sh[DI / 32], sh2[DI / 32];
#pragma unroll
    for (int o = 16; o; o >>= 1) {
        s  += __shfl_xor_sync(0xffffffffu, s,  o);
        s2 += __shfl_xor_sync(0xffffffffu, s2, o);
    }
    if ((t & 31) == 0) { sh[t >> 5] = s; sh2[t >> 5] = s2; }
    __syncthreads();
    float mean = 0.f, m2 = 0.f;
#pragma unroll
    for (int i = 0; i < DI / 32; i++) { mean += sh[i]; m2 += sh2[i]; }
    mean *= (1.0f / DI);
    float var = m2 * (1.0f / DI) - mean * mean;
    float inv = rsqrtf(var + 1e-5f);
    float ln  = (v - mean) * inv * g[t] + b[t];
    float zz  = xz[row * (2 * DI) + DI + t];
    out[row * DI + t] = ln * silu_f(zz);
}

// ============ TF32 tensor-core GEMM: C[M,N] = A[M,K(lda)] * W[N,K]^T ==========
// 128x64 block tile, 256 threads = 8 warps, each warp a 32x32 tile made of
// 2x4 m16n8k8 tf32 mma atoms. BK=32. Requires M%128==0, N%64==0, K%32==0.
// ACT: 0 none, 1 softplus, 2 gelu
#define TBM 128
#define TBN 64
#define TBK 32

template <int ACT, bool HAS_BIAS, bool HAS_RES>
__global__ __launch_bounds__(256)
void gemm_tc(const float* __restrict__ A, int lda,
             const float* __restrict__ W,
             const float* __restrict__ bias,
             const float* __restrict__ res,
             float* __restrict__ Cout,
             int M, int N, int K) {
    __shared__ float As[TBM][TBK + 4];   // [m][k], pad 36 -> conflict-free frags
    __shared__ float Ws[TBN][TBK + 4];   // [n][k]

    int t    = threadIdx.x;
    int lane = t & 31;
    int wid  = t >> 5;
    int wm   = (wid & 3) * 32;           // warp M offset in tile
    int wn   = (wid >> 2) * 32;          // warp N offset in tile
    int gid  = lane >> 2;                // 0..7
    int tig  = lane & 3;                 // 0..3
    int row0 = blockIdx.y * TBM;
    int col0 = blockIdx.x * TBN;

    int lr = t >> 3;                     // 0..31
    int lc = (t & 7) * 4;                // 0,4,..,28

    float acc[2][4][4];
#pragma unroll
    for (int i = 0; i < 2; i++)
#pragma unroll
        for (int j = 0; j < 4; j++)
#pragma unroll
            for (int q = 0; q < 4; q++) acc[i][j][q] = 0.f;

    float4 ra[4], rw[2];
#pragma unroll
    for (int i = 0; i < 4; i++)
        ra[i] = *(const float4*)&A[(row0 + lr + i * 32) * lda + lc];
#pragma unroll
    for (int i = 0; i < 2; i++)
        rw[i] = *(const float4*)&W[(col0 + lr + i * 32) * K + lc];

    for (int k0 = 0; k0 < K; k0 += TBK) {
        __syncthreads();
#pragma unroll
        for (int i = 0; i < 4; i++) {
            As[lr + i * 32][lc + 0] = __uint_as_float(tf32_of(ra[i].x));
            As[lr + i * 32][lc + 1] = __uint_as_float(tf32_of(ra[i].y));
            As[lr + i * 32][lc + 2] = __uint_as_float(tf32_of(ra[i].z));
            As[lr + i * 32][lc + 3] = __uint_as_float(tf32_of(ra[i].w));
        }
#pragma unroll
        for (int i = 0; i < 2; i++) {
            Ws[lr + i * 32][lc + 0] = __uint_as_float(tf32_of(rw[i].x));
            Ws[lr + i * 32][lc + 1] = __uint_as_float(tf32_of(rw[i].y));
            Ws[lr + i * 32][lc + 2] = __uint_as_float(tf32_of(rw[i].z));
            Ws[lr + i * 32][lc + 3] = __uint_as_float(tf32_of(rw[i].w));
        }
        __syncthreads();

        int kn = k0 + TBK;
        if (kn < K) {
#pragma unroll
            for (int i = 0; i < 4; i++)
                ra[i] = *(const float4*)&A[(row0 + lr + i * 32) * lda + kn + lc];
#pragma unroll
            for (int i = 0; i < 2; i++)
                rw[i] = *(const float4*)&W[(col0 + lr + i * 32) * K + kn + lc];
        }

#pragma unroll
        for (int k8 = 0; k8 < 4; k8++) {
            int kk = k8 * 8;
            uint32_t af[2][4], bf[4][2];
#pragma unroll
            for (int i = 0; i < 2; i++) {
                int r = wm + i * 16 + gid;
                af[i][0] = __float_as_uint(As[r][kk + tig]);
                af[i][1] = __float_as_uint(As[r + 8][kk + tig]);
                af[i][2] = __float_as_uint(As[r][kk + tig + 4]);
                af[i][3] = __float_as_uint(As[r + 8][kk + tig + 4]);
            }
#pragma unroll
            for (int j = 0; j < 4; j++) {
                int n = wn + j * 8 + gid;
                bf[j][0] = __float_as_uint(Ws[n][kk + tig]);
                bf[j][1] = __float_as_uint(Ws[n][kk + tig + 4]);
            }
#pragma unroll
            for (int i = 0; i < 2; i++)
#pragma unroll
                for (int j = 0; j < 4; j++)
                    mma_tf32(acc[i][j][0], acc[i][j][1], acc[i][j][2], acc[i][j][3],
                             af[i][0], af[i][1], af[i][2], af[i][3],
                             bf[j][0], bf[j][1]);
        }
    }

    // epilogue: c0,c1 -> (row, col..col+1); c2,c3 -> (row+8, col..col+1)
#pragma unroll
    for (int i = 0; i < 2; i++) {
        int rA = row0 + wm + i * 16 + gid;
#pragma unroll
        for (int j = 0; j < 4; j++) {
            int col = col0 + wn + j * 8 + tig * 2;
            float b0 = 0.f, b1 = 0.f;
            if (HAS_BIAS) { b0 = bias[col]; b1 = bias[col + 1]; }
            float v0 = acc[i][j][0] + b0;
            float v1 = acc[i][j][1] + b1;
            float v2 = acc[i][j][2] + b0;
            float v3 = acc[i][j][3] + b1;
            if (ACT == 1) { v0 = softplus_f(v0); v1 = softplus_f(v1);
                            v2 = softplus_f(v2); v3 = softplus_f(v3); }
            else if (ACT == 2) { v0 = gelu_f(v0); v1 = gelu_f(v1);
                                 v2 = gelu_f(v2); v3 = gelu_f(v3); }
            if (HAS_RES) {
                float2 r0 = *(const float2*)&res[rA * N + col];
                float2 r1 = *(const float2*)&res[(rA + 8) * N + col];
                v0 += r0.x; v1 += r0.y; v2 += r1.x; v3 += r1.y;
            }
            *(float2*)&Cout[rA * N + col]       = make_float2(v0, v1);
            *(float2*)&Cout[(rA + 8) * N + col] = make_float2(v2, v3);
        }
    }
}

// ---------------- depthwise 3x3 conv + bias + SiLU, scatter to zigzag order ----
__global__ void conv_silu_kernel(const float* __restrict__ xz,
                                 const float* __restrict__ cw,
                                 const float* __restrict__ cb,
                                 const int* __restrict__ perm_rev,
                                 float* __restrict__ u) {
    int bp = blockIdx.x;            // b*1024 + p
    int b  = bp >> 10;
    int p  = bp & 1023;
    int h  = p >> 5;
    int w  = p & 31;
    int d  = threadIdx.x;           // 384
    float acc = cb[d];
#pragma unroll
    for (int kh = 0; kh < 3; kh++) {
        int nh = h + kh - 1;
        if ((unsigned)nh >= (unsigned)Hh) continue;
#pragma unroll
        for (int kw = 0; kw < 3; kw++) {
            int nw = w + kw - 1;
            if ((unsigned)nw >= (unsigned)Ww) continue;
            acc = fmaf(cw[d * 9 + kh * 3 + kw],
                       xz[((b << 10) + (nh << 5) + nw) * (2 * DI) + d], acc);
        }
    }
    u[((b << 10) + perm_rev[p]) * DI + d] = silu_f(acc);
}

// ---------------- pad x_proj_w [44,384] -> [64,384] (rows 44..63 zero) --------
__global__ void padw_kernel(const float* __restrict__ xw,
                            float* __restrict__ xw64) {
    int i = blockIdx.x * 256 + threadIdx.x;
    if (i < 64 * DI) {
        int r = i / DI;
        xw64[i] = (r < 44) ? xw[i] : 0.f;
    }
}

// ---------------- dt_proj + softplus from padded xdbl (16 rows per block) -----
__global__ __launch_bounds__(256)
void dt_kernel(const float* __restrict__ xdbl64,  // [ROWS,64]
               const float* __restrict__ dtw,     // [384,12]
               const float* __restrict__ dtb,     // [384]
               float* __restrict__ delta) {       // [ROWS,DI]
    __shared__ float sdt[16][13];
    int t    = threadIdx.x;
    int row0 = blockIdx.x * 16;
    if (t < 192) {
        int r = t / 12, c = t % 12;
        sdt[r][c] = xdbl64[(row0 + r) * 64 + c];
    }
    __syncthreads();
#pragma unroll
    for (int i = 0; i < 24; i++) {
        int idx = t + i * 256;
        int r   = idx / DI;
        int d   = idx % DI;
        float acc = dtb[d];
        const float* dw = &dtw[d * Rr];
#pragma unroll
        for (int j = 0; j < Rr; j++)
            acc = fmaf(sdt[r][j], dw[j], acc);
        delta[(row0 + r) * DI + d] = softplus_f(acc);
    }
}

// ---------------- selective scan: one 16-lane group per (b,d) -----------------
__global__ void scan_kernel(const float* __restrict__ xdbl,   // [ROWS,64]
                            const float* __restrict__ delta,
                            const float* __restrict__ u,
                            const float* __restrict__ A_log,
                            const float* __restrict__ Dp,
                            const int* __restrict__ perm,
                            float* __restrict__ y) {
    int t = threadIdx.x;                  // 256
    int g = blockIdx.x * 16 + (t >> 4);   // group id: 0..3071
    int s = t & 15;
    int b = g / DI;
    int d = g % DI;
    float A  = -expf(A_log[d * Ss + s]);
    float Dd = Dp[d];
    float h  = 0.f;
    int base = b * Ll;

    // prefetch l = 0
    float dl = delta[base * DI + d];
    float ul = u[base * DI + d];
    float Bs = xdbl[base * 64 + Rr + s];
    float Cs = xdbl[base * 64 + Rr + Ss + s];
    int   pl = perm[0];

    for (int l = 0; l < Ll; l++) {
        float dl2, ul2, Bs2, Cs2; int pl2;
        if (l + 1 < Ll) {
            int row = base + l + 1;
            dl2 = delta[row * DI + d];
            ul2 = u[row * DI + d];
            Bs2 = xdbl[row * 64 + Rr + s];
            Cs2 = xdbl[row * 64 + Rr + Ss + s];
            pl2 = perm[l + 1];
        }
        float dA = __expf(dl * A);
        h = fmaf(dA, h, dl * ul * Bs);
        float yv = h * Cs;
#pragma unroll
        for (int o = 8; o; o >>= 1) yv += __shfl_xor_sync(0xffffffffu, yv, o, 16);
        if (s == 0) y[(base + pl) * DI + d] = yv + ul * Dd;
        dl = dl2; ul = ul2; Bs = Bs2; Cs = Cs2; pl = pl2;
    }
}

// ---------------- launcher ----------------
extern "C" void kernel_launch(void* const* d_in, const int* in_sizes, int n_in,
                              void* d_out, int out_size) {
    const float* x          = (const float*)d_in[0];
    const int*   perm       = (const int*)  d_in[1];
    const int*   perm_rev   = (const int*)  d_in[2];
    const float* ln1_g      = (const float*)d_in[3];
    const float* ln1_b      = (const float*)d_in[4];
    const float* in_proj_w  = (const float*)d_in[5];
    const float* conv_w     = (const float*)d_in[6];
    const float* conv_b     = (const float*)d_in[7];
    const float* x_proj_w   = (const float*)d_in[8];
    const float* dt_proj_w  = (const float*)d_in[9];
    const float* dt_proj_b  = (const float*)d_in[10];
    const float* A_log      = (const float*)d_in[11];
    const float* Dp         = (const float*)d_in[12];
    const float* out_norm_g = (const float*)d_in[13];
    const float* out_norm_b = (const float*)d_in[14];
    const float* out_proj_w = (const float*)d_in[15];
    const float* ln2_g      = (const float*)d_in[16];
    const float* ln2_b      = (const float*)d_in[17];
    const float* fc1_w      = (const float*)d_in[18];
    const float* fc1_b      = (const float*)d_in[19];
    const float* fc2_w      = (const float*)d_in[20];
    const float* fc2_b      = (const float*)d_in[21];
    float* out = (float*)d_out;

    float *hx, *xz, *u, *xw64, *xdbl, *delta, *y, *xmid, *h2, *m;
    cudaGetSymbolAddress((void**)&hx,    g_hx);
    cudaGetSymbolAddress((void**)&xz,    g_xz);
    cudaGetSymbolAddress((void**)&u,     g_u);
    cudaGetSymbolAddress((void**)&xw64,  g_xw64);
    cudaGetSymbolAddress((void**)&xdbl,  g_xdbl);
    cudaGetSymbolAddress((void**)&delta, g_delta);
    cudaGetSymbolAddress((void**)&y,     g_y);
    cudaGetSymbolAddress((void**)&xmid,  g_xmid);
    cudaGetSymbolAddress((void**)&h2,    g_h2);
    cudaGetSymbolAddress((void**)&m,     g_m);

    // 0. pad x_proj weights (tiny; overlaps nothing downstream until step 4)
    padw_kernel<<<(64 * DI + 255) / 256, 256>>>(x_proj_w, xw64);
    // 1. LN1
    ln_kernel<Cc><<<ROWS, Cc>>>(x, ln1_g, ln1_b, hx);
    // 2. in_proj: [8192,192] x [768,192]^T -> xz [8192,768]   (TF32 TC)
    gemm_tc<0, false, false><<<dim3((2 * DI) / TBN, ROWS / TBM), 256>>>(
        hx, Cc, in_proj_w, nullptr, nullptr, xz, ROWS, 2 * DI, Cc);
    // 3. depthwise conv + SiLU + zigzag scatter -> u [8192,384]
    conv_silu_kernel<<<ROWS, DI>>>(xz, conv_w, conv_b, perm_rev, u);
    // 4. x_proj as TF32 GEMM: [8192,384] x [64,384]^T -> xdbl [8192,64]
    gemm_tc<0, false, false><<<dim3(1, ROWS / TBM), 256>>>(
        u, DI, xw64, nullptr, nullptr, xdbl, ROWS, 64, DI);
    // 5. dt_proj + softplus -> delta
    dt_kernel<<<ROWS / 16, 256>>>(xdbl, dt_proj_w, dt_proj_b, delta);
    // 6. selective scan + Dp skip + un-zigzag scatter -> y (spatial order)
    scan_kernel<<<(Bn * DI) / 16, 256>>>(xdbl, delta, u, A_log, Dp, perm, y);
    // 7. out_norm LN + silu(z) gate (in-place on y)
    gate_ln_kernel<<<ROWS, DI>>>(y, xz, out_norm_g, out_norm_b, y);
    // 8. out_proj + residual x -> xmid [8192,192]   (TF32 TC)
    gemm_tc<0, false, true><<<dim3(Cc / TBN, ROWS / TBM), 256>>>(
        y, DI, out_proj_w, nullptr, x, xmid, ROWS, Cc, DI);
    // 9. LN2
    ln_kernel<Cc><<<ROWS, Cc>>>(xmid, ln2_g, ln2_b, h2);
    // 10. fc1 + bias + gelu -> m [8192,768]   (TF32 TC)
    gemm_tc<2, true, false><<<dim3(HID / TBN, ROWS / TBM), 256>>>(
        h2, Cc, fc1_w, fc1_b, nullptr, m, ROWS, HID, Cc);
    // 11. fc2 + bias + residual xmid -> out [8192,192]   (TF32 TC)
    gemm_tc<0, true, true><<<dim3(Cc / TBN, ROWS / TBM), 256>>>(
        m, HID, fc2_w, fc2_b, xmid, out, ROWS, Cc, HID);
}